// round 15
// baseline (speedup 1.0000x reference)
#include <cuda_runtime.h>
#include <cuda_bf16.h>
#include <math.h>
#include <stdint.h>

// Shapes: B=4, N=256, F=64, H=256, A=16, T=3
#define Bn 4
#define Nn 256
#define Fn 64
#define Hn 256
#define An 16
#define Tn 3
#define BN 1024
#define NC 1280
#define STAGES 3

typedef unsigned long long u64;

// ---------------- scratch (device globals) -----------------------------------
__device__ float d_XT  [Fn*BN];      // X^T        [64][1024]
__device__ float d_tT  [Hn*BN];      // pre-hidden^T
__device__ float d_hT  [Hn*BN];      // h^T
__device__ float d_aT  [Hn*BN];      // agg0^T
__device__ float d_M2T [Hn*Hn];      // msg_W2^T
__device__ float d_big2[BN*512];     // [hi+b1 | hj] row-major
__device__ float d_ghT [768*BN];     // gh^T (+bhh)
__device__ float d_giT [768*BN];     // gi^T
__device__ float d_deg [BN];
__device__ float d_Wc  [Hn*768];     // msg_W2 @ gru_Wih (row-major)
__device__ float d_bc  [768];        // msg_b2 @ gru_Wih
__device__ float d_Wcat[Hn*NC];      // [W1_i | W1_j | Whh] row-major
__device__ float d_bcat[NC];

// ---------------- helpers ------------------------------------------------------
#define FMA2(acc, a, b) \
    asm("fma.rn.f32x2 %0, %1, %2, %0;" : "+l"(acc) : "l"(a), "l"(b))
#define PACKDUP(d, s) \
    asm("mov.b64 %0, {%1, %1};" : "=l"(d) : "f"(s))
#define UNPACK2(lo, hi, s) \
    asm("mov.b64 {%0, %1}, %2;" : "=f"(lo), "=f"(hi) : "l"(s))

__device__ __forceinline__ void cpa16(void* s, const void* g) {
    uint32_t sa = (uint32_t)__cvta_generic_to_shared(s);
    asm volatile("cp.async.ca.shared.global [%0], [%1], 16;" :: "r"(sa), "l"(g));
}

// ---------------- pipelined fp32 GEMM, 128x64 tile, 256 thr --------------------
// C = f(A@B + bias + rowS*colV); A TRANSPOSED At[k][m] (ld ldaT); B row-major KxN.
// Warps 4(m)x2(n): warp tile 32x32. Thread: 4 rows x 8 contiguous cols = 32 FMA2.
// 3-stage cp.async pipeline, K-chunks of 16 (K mult 16, >=32). M mult 128, N mult 64.
// Block cols < splitCol -> Crow[r][c] (ld ldC); else CtrT[(c-splitCol)][r] (ld ldT).
__global__ void __launch_bounds__(256, 2)
gemmF(const float* __restrict__ At, int ldaT,
      const float* __restrict__ Bm, int N, int K,
      const float* __restrict__ bias,
      const float* __restrict__ rowS, const float* __restrict__ colV,
      float* __restrict__ Crow, int ldC, int splitCol,
      float* __restrict__ CtrT, int ldT, int doRelu)
{
    __shared__ __align__(16) float As[STAGES][16][132];   // 128 m + 4 pad
    __shared__ __align__(16) float Bs[STAGES][16][64];

    int tid = threadIdx.x;
    int l = tid & 31, w = tid >> 5;
    int wm = w >> 1, wn = w & 1;
    int rg = l >> 2, cg = l & 3;
    int row0 = blockIdx.y * 128, col0 = blockIdx.x * 64;

    // loaders: A 512 float4/chunk (2/thread), B 256 float4 (1/thread)
    int ak0 = tid >> 5, am0 = (tid & 31) << 2;           // idx = tid
    int ak1 = (tid + 256) >> 5, am1 = ((tid + 256) & 31) << 2;
    int bk = tid >> 4, bn = (tid & 15) << 2;
    const float* Abase = At + row0;
    const float* Bbase = Bm + col0;

    u64 acc[4][4];     // 4 rows x 4 col-pairs (8 cols)
    #pragma unroll
    for (int i = 0; i < 4; i++)
        #pragma unroll
        for (int j = 0; j < 4; j++) acc[i][j] = 0ull;

    int nch = K >> 4;
    #pragma unroll
    for (int p = 0; p < 2; p++) {
        int kc = p << 4;
        cpa16(&As[p][ak0][am0], Abase + (size_t)(kc + ak0) * ldaT + am0);
        cpa16(&As[p][ak1][am1], Abase + (size_t)(kc + ak1) * ldaT + am1);
        cpa16(&Bs[p][bk][bn],   Bbase + (size_t)(kc + bk) * N + bn);
        asm volatile("cp.async.commit_group;");
    }

    int mrow = wm * 32 + rg * 4;
    int ncol = wn * 32 + cg * 8;
    int s = 0;
    for (int ch = 0; ch < nch; ch++) {
        if (ch < nch - 1) asm volatile("cp.async.wait_group 1;");
        else              asm volatile("cp.async.wait_group 0;");
        __syncthreads();

        if (ch + 2 < nch) {
            int s2 = s + 2; if (s2 >= STAGES) s2 -= STAGES;
            int kc = (ch + 2) << 4;
            cpa16(&As[s2][ak0][am0], Abase + (size_t)(kc + ak0) * ldaT + am0);
            cpa16(&As[s2][ak1][am1], Abase + (size_t)(kc + ak1) * ldaT + am1);
            cpa16(&Bs[s2][bk][bn],   Bbase + (size_t)(kc + bk) * N + bn);
            asm volatile("cp.async.commit_group;");
        }

        #pragma unroll
        for (int k = 0; k < 16; k++) {
            float4 av = *(float4*)&As[s][k][mrow];
            ulonglong2 q0 = *(ulonglong2*)&Bs[s][k][ncol];
            ulonglong2 q1 = *(ulonglong2*)&Bs[s][k][ncol + 4];
            u64 a0, a1, a2, a3;
            PACKDUP(a0, av.x); PACKDUP(a1, av.y); PACKDUP(a2, av.z); PACKDUP(a3, av.w);
            FMA2(acc[0][0], a0, q0.x); FMA2(acc[0][1], a0, q0.y);
            FMA2(acc[0][2], a0, q1.x); FMA2(acc[0][3], a0, q1.y);
            FMA2(acc[1][0], a1, q0.x); FMA2(acc[1][1], a1, q0.y);
            FMA2(acc[1][2], a1, q1.x); FMA2(acc[1][3], a1, q1.y);
            FMA2(acc[2][0], a2, q0.x); FMA2(acc[2][1], a2, q0.y);
            FMA2(acc[2][2], a2, q1.x); FMA2(acc[2][3], a2, q1.y);
            FMA2(acc[3][0], a3, q0.x); FMA2(acc[3][1], a3, q0.y);
            FMA2(acc[3][2], a3, q1.x); FMA2(acc[3][3], a3, q1.y);
        }
        s++; if (s >= STAGES) s = 0;
    }

    // epilogue: 4 rows x 8 contiguous cols
    float vv[4][8];
    #pragma unroll
    for (int i = 0; i < 4; i++) {
        UNPACK2(vv[i][0], vv[i][1], acc[i][0]);
        UNPACK2(vv[i][2], vv[i][3], acc[i][1]);
        UNPACK2(vv[i][4], vv[i][5], acc[i][2]);
        UNPACK2(vv[i][6], vv[i][7], acc[i][3]);
    }
    int c0 = col0 + ncol;
    int r0 = row0 + mrow;
    #pragma unroll
    for (int j = 0; j < 8; j++) {
        float bj  = bias ? bias[c0 + j] : 0.f;
        float cvj = rowS ? colV[c0 + j] : 0.f;
        #pragma unroll
        for (int i = 0; i < 4; i++) {
            float rs = rowS ? rowS[r0 + i] : 0.f;
            float v = vv[i][j] + bj + rs * cvj;
            if (doRelu) v = fmaxf(v, 0.f);
            vv[i][j] = v;
        }
    }
    if (c0 < splitCol) {
        #pragma unroll
        for (int i = 0; i < 4; i++) {
            float4 o0 = {vv[i][0], vv[i][1], vv[i][2], vv[i][3]};
            float4 o1 = {vv[i][4], vv[i][5], vv[i][6], vv[i][7]};
            *(float4*)(Crow + (size_t)(r0 + i) * ldC + c0)     = o0;
            *(float4*)(Crow + (size_t)(r0 + i) * ldC + c0 + 4) = o1;
        }
    } else {
        #pragma unroll
        for (int j = 0; j < 8; j++) {
            float4 o = {vv[0][j], vv[1][j], vv[2][j], vv[3][j]};
            *(float4*)(CtrT + (size_t)(c0 + j - splitCol) * ldT + r0) = o;
        }
    }
}

// ---------------- prep: transposes + Wcat/bcat -------------------------------
__global__ void prep(const float* __restrict__ X, const float* __restrict__ msgW2,
                     const float* __restrict__ msgW1, const float* __restrict__ Whh,
                     const float* __restrict__ msgb1, const float* __restrict__ bhh,
                     float* __restrict__ XT, float* __restrict__ M2T,
                     float* __restrict__ Wcat, float* __restrict__ bcat)
{
    int blk = blockIdx.x, t = threadIdx.x;
    if (blk < 256) {
        int i = blk * 256 + t;
        int k = i >> 10, m = i & 1023;
        XT[i] = X[(size_t)m * Fn + k];
    } else if (blk < 512) {
        int i = (blk - 256) * 256 + t;
        int k = i >> 8, m = i & 255;
        M2T[i] = msgW2[(size_t)m * Hn + k];
    } else {
        int i = (blk - 512) * 256 + t;
        int k = i / NC, n = i % NC;
        float v;
        if (n < 256)      v = msgW1[(size_t)k * Hn + n];
        else if (n < 512) v = msgW1[(size_t)(256 + k) * Hn + (n - 256)];
        else              v = Whh[(size_t)k * 768 + (n - 512)];
        Wcat[i] = v;
        if (i < NC)
            bcat[i] = i < 256 ? msgb1[i] : (i < 512 ? 0.f : bhh[i - 512]);
    }
}

// ---------------- E-aggregation ----------------------------------------------
#define IT 8
__global__ void eagg(const float* __restrict__ big2, const int* __restrict__ adj,
                     float* __restrict__ aT, float* __restrict__ deg)
{
    int b  = blockIdx.y;
    int i0 = blockIdx.x * IT;
    int h  = threadIdx.x;

    __shared__ float adjf[Nn][IT];

    float hir[IT], acc[IT];
    #pragma unroll
    for (int t = 0; t < IT; t++) {
        adjf[h][t] = (float)adj[((size_t)(b * Nn + i0 + t)) * Nn + h];
        hir[t] = big2[((size_t)(b * Nn + i0 + t)) * 512 + h];
        acc[t] = 0.f;
    }
    __syncthreads();

    const float* hjb = big2 + (size_t)b * Nn * 512 + 256;
    #pragma unroll 2
    for (int j = 0; j < Nn; j++) {
        float hjv = hjb[(size_t)j * 512 + h];
        float4 a04 = *(float4*)&adjf[j][0];
        float4 a47 = *(float4*)&adjf[j][4];
        acc[0] += a04.x * fmaxf(hir[0] + hjv, 0.f);
        acc[1] += a04.y * fmaxf(hir[1] + hjv, 0.f);
        acc[2] += a04.z * fmaxf(hir[2] + hjv, 0.f);
        acc[3] += a04.w * fmaxf(hir[3] + hjv, 0.f);
        acc[4] += a47.x * fmaxf(hir[4] + hjv, 0.f);
        acc[5] += a47.y * fmaxf(hir[5] + hjv, 0.f);
        acc[6] += a47.z * fmaxf(hir[6] + hjv, 0.f);
        acc[7] += a47.w * fmaxf(hir[7] + hjv, 0.f);
    }

    #pragma unroll
    for (int t = 0; t < IT; t++)
        aT[(size_t)h * BN + b * Nn + i0 + t] = acc[t];

    if (h < IT) {
        float s = 0.f;
        for (int j = 0; j < Nn; j++) s += adjf[j][h];
        deg[b * Nn + i0 + h] = s;
    }
}

// ---------------- bc = msg_b2 @ gru_Wih (one warp per output) ----------------
__global__ void bck(const float* __restrict__ b2, const float* __restrict__ Wih,
                    float* __restrict__ bc)
{
    int warp = (blockIdx.x * blockDim.x + threadIdx.x) >> 5;
    int lane = threadIdx.x & 31;
    float s = 0.f;
    for (int k = lane; k < Hn; k += 32)
        s += b2[k] * Wih[(size_t)k * 768 + warp];
    #pragma unroll
    for (int o = 16; o; o >>= 1) s += __shfl_xor_sync(0xffffffffu, s, o);
    if (lane == 0) bc[warp] = s;
}

// ---------------- GRU elementwise (coalesced on transposed layouts) ----------
__global__ void gru(const float* __restrict__ giT, const float* __restrict__ ghT,
                    float* __restrict__ hT)
{
    int id = blockIdx.x * 256 + threadIdx.x;
    int m = id & 1023, c = id >> 10;
    float ir = giT[(size_t)c * BN + m];
    float iz = giT[(size_t)(c + 256) * BN + m];
    float in = giT[(size_t)(c + 512) * BN + m];
    float hr = ghT[(size_t)c * BN + m];
    float hz = ghT[(size_t)(c + 256) * BN + m];
    float hn = ghT[(size_t)(c + 512) * BN + m];
    float r = 1.f / (1.f + __expf(-(ir + hr)));
    float z = 1.f / (1.f + __expf(-(iz + hz)));
    float n = tanhf(in + r * hn);
    hT[id] = (1.f - z) * n + z * hT[id];
}

// ---------------- readout ------------------------------------------------------
__global__ void readout(const float* __restrict__ hT,
                        const float* __restrict__ W1, const float* __restrict__ b1,
                        const float* __restrict__ W2, const float* __restrict__ b2,
                        float* __restrict__ out)
{
    __shared__ float gsh[Hn];
    __shared__ float hsh[Hn];
    int b = blockIdx.x, t = threadIdx.x;

    float s = 0.f;
    const float* hrow = hT + (size_t)t * BN + b * Nn;
    #pragma unroll 4
    for (int i = 0; i < Nn; i++) s += hrow[i];
    gsh[t] = s;
    __syncthreads();

    float s2 = b1[t];
    for (int k = 0; k < Hn; k++) s2 += gsh[k] * W1[(size_t)k * Hn + t];
    hsh[t] = fmaxf(s2, 0.f);
    __syncthreads();

    if (t < An) {
        float s3 = b2[t];
        for (int k = 0; k < Hn; k++) s3 += hsh[k] * W2[(size_t)k * An + t];
        out[b * An + t] = s3;
    }
}

// ---------------- host launch ---------------------------------------------------
extern "C" void kernel_launch(void* const* d_in, const int* in_sizes, int n_in,
                              void* d_out, int out_size)
{
    const float* X       = (const float*)d_in[0];
    const int*   adj     = (const int*)  d_in[1];
    const float* pre_W1  = (const float*)d_in[2];
    const float* pre_b1  = (const float*)d_in[3];
    const float* pre_W2  = (const float*)d_in[4];
    const float* pre_b2  = (const float*)d_in[5];
    const float* msg_W1  = (const float*)d_in[6];
    const float* msg_b1  = (const float*)d_in[7];
    const float* msg_W2  = (const float*)d_in[8];
    const float* msg_b2  = (const float*)d_in[9];
    const float* gru_Wih = (const float*)d_in[10];
    const float* gru_Whh = (const float*)d_in[11];
    const float* gru_bih = (const float*)d_in[12];
    const float* gru_bhh = (const float*)d_in[13];
    const float* ro_W1   = (const float*)d_in[14];
    const float* ro_b1   = (const float*)d_in[15];
    const float* ro_W2   = (const float*)d_in[16];
    const float* ro_b2   = (const float*)d_in[17];

    float *XT,*tT,*hT,*aT,*M2T,*big2,*ghT,*giT,*deg,*Wc,*bc,*Wcat,*bcat;
    cudaGetSymbolAddress((void**)&XT,  d_XT);
    cudaGetSymbolAddress((void**)&tT,  d_tT);
    cudaGetSymbolAddress((void**)&hT,  d_hT);
    cudaGetSymbolAddress((void**)&aT,  d_aT);
    cudaGetSymbolAddress((void**)&M2T, d_M2T);
    cudaGetSymbolAddress((void**)&big2,d_big2);
    cudaGetSymbolAddress((void**)&ghT, d_ghT);
    cudaGetSymbolAddress((void**)&giT, d_giT);
    cudaGetSymbolAddress((void**)&deg, d_deg);
    cudaGetSymbolAddress((void**)&Wc,  d_Wc);
    cudaGetSymbolAddress((void**)&bc,  d_bc);
    cudaGetSymbolAddress((void**)&Wcat,d_Wcat);
    cudaGetSymbolAddress((void**)&bcat,d_bcat);

    // prep: XT, M2T, Wcat, bcat; bc
    prep<<<512 + Hn * NC / 256, 256>>>(X, msg_W2, msg_W1, gru_Whh, msg_b1, gru_bhh,
                                       XT, M2T, Wcat, bcat);
    bck<<<96, 256>>>(msg_b2, gru_Wih, bc);

    // Wc = msg_W2 @ gru_Wih: M=256, N=768, K=256 -> grid (12, 2)
    gemmF<<<dim3(768/64, 256/128), 256>>>(M2T, Hn, gru_Wih, 768, Hn,
                                          nullptr, nullptr, nullptr,
                                          Wc, 768, 768, nullptr, 0, 0);

    // pre-MLP: tT = relu(X@W1+b1)^T ; hT = (t@W2+b2)^T   -> grid (4, 8)
    gemmF<<<dim3(256/64, BN/128), 256>>>(XT, BN, pre_W1, Hn, Fn,
                                         pre_b1, nullptr, nullptr,
                                         nullptr, 0, 0, tT, BN, 1);
    gemmF<<<dim3(256/64, BN/128), 256>>>(tT, BN, pre_W2, Hn, Hn,
                                         pre_b2, nullptr, nullptr,
                                         nullptr, 0, 0, hT, BN, 0);

    for (int it = 0; it < Tn; it++) {
        // [hi+b1 | hj] -> big2 (row-major), gh+bhh -> ghT (transposed). grid (20, 8)
        gemmF<<<dim3(NC/64, BN/128), 256>>>(hT, BN, Wcat, NC, Hn,
                                            bcat, nullptr, nullptr,
                                            big2, 512, 512, ghT, BN, 0);
        eagg<<<dim3(Nn / IT, Bn), 256>>>(big2, adj, aT, deg);
        // giT = (agg0 @ Wc + deg*bc + bih)^T. grid (12, 8)
        gemmF<<<dim3(768/64, BN/128), 256>>>(aT, BN, Wc, 768, Hn,
                                             gru_bih, deg, bc,
                                             nullptr, 0, 0, giT, BN, 0);
        gru<<<Hn * BN / 256, 256>>>(giT, ghT, hT);
    }

    readout<<<Bn, 256>>>(hT, ro_W1, ro_b1, ro_W2, ro_b2, (float*)d_out);
}

// round 16
// speedup vs baseline: 1.1653x; 1.1653x over previous
#include <cuda_runtime.h>
#include <cuda_bf16.h>
#include <math.h>
#include <stdint.h>

// Shapes: B=4, N=256, F=64, H=256, A=16, T=3
#define Bn 4
#define Nn 256
#define Fn 64
#define Hn 256
#define An 16
#define Tn 3
#define BN 1024
#define NC 1280
#define STAGES 3

typedef unsigned long long u64;

// ---------------- scratch (device globals) -----------------------------------
__device__ float d_XT  [Fn*BN];      // X^T        [64][1024]
__device__ float d_tT  [Hn*BN];      // pre-hidden^T
__device__ float d_hT  [Hn*BN];      // h^T
__device__ float d_aT  [Hn*BN];      // agg0^T
__device__ float d_M2T [Hn*Hn];      // msg_W2^T
__device__ float d_big2[BN*512];     // [hi+b1 | hj] row-major
__device__ float d_ghT [768*BN];     // gh^T (+bhh)
__device__ float d_giT [768*BN];     // gi^T
__device__ float d_deg [BN];
__device__ float d_Wc  [Hn*768];     // msg_W2 @ gru_Wih (row-major)
__device__ float d_bc  [768];        // msg_b2 @ gru_Wih
__device__ float d_Wcat[Hn*NC];      // [W1_i | W1_j | Whh] row-major
__device__ float d_bcat[NC];

// ---------------- helpers ------------------------------------------------------
#define FMA2(acc, a, b) \
    asm("fma.rn.f32x2 %0, %1, %2, %0;" : "+l"(acc) : "l"(a), "l"(b))
#define PACKDUP(d, s) \
    asm("mov.b64 %0, {%1, %1};" : "=l"(d) : "f"(s))
#define UNPACK2(lo, hi, s) \
    asm("mov.b64 {%0, %1}, %2;" : "=f"(lo), "=f"(hi) : "l"(s))

__device__ __forceinline__ void cpa16(void* s, const void* g) {
    uint32_t sa = (uint32_t)__cvta_generic_to_shared(s);
    asm volatile("cp.async.ca.shared.global [%0], [%1], 16;" :: "r"(sa), "l"(g));
}

// ---------------- pipelined fp32 GEMM, 64x32 tile, 64 thr (2 warps) -----------
// C = f(A@B + bias + rowS*colV); A TRANSPOSED At[k][m] (ld ldaT); B row-major KxN.
// Warp w owns rows w*32..+31, all 32 cols. Thread: 4 rows x 8 contiguous cols
// (16 FMA2 + 3 LDS.128 + 4 PACKDUP per k-step — same profile as the 321us best).
// 3-stage cp.async pipeline, K-chunks of 16 (K mult 16, K>=48 for full pipeline,
// K=64 ok). M mult 64, N mult 32.
// Block cols < splitCol -> Crow[r][c] (ld ldC); else CtrT[(c-splitCol)][r] (ld ldT).
__global__ void __launch_bounds__(64)
gemmS(const float* __restrict__ At, int ldaT,
      const float* __restrict__ Bm, int N, int K,
      const float* __restrict__ bias,
      const float* __restrict__ rowS, const float* __restrict__ colV,
      float* __restrict__ Crow, int ldC, int splitCol,
      float* __restrict__ CtrT, int ldT, int doRelu)
{
    __shared__ __align__(16) float As[STAGES][16][68];   // 64 m + 4 pad
    __shared__ __align__(16) float Bs[STAGES][16][32];

    int tid = threadIdx.x;
    int l = tid & 31, w = tid >> 5;          // 2 warps
    int rg = l >> 2, cg = l & 3;             // 8 row-groups x 4 col-groups
    int row0 = blockIdx.y * 64, col0 = blockIdx.x * 32;

    // loaders (64 thr): A chunk 16x64 = 256 f4 (4/thread); B 16x32 = 128 f4 (2/thread)
    int ar0 = tid >> 4,          as0 = (tid & 15) << 2;
    int ar1 = (tid + 64) >> 4,   as1 = ((tid + 64) & 15) << 2;
    int ar2 = (tid + 128) >> 4,  as2 = ((tid + 128) & 15) << 2;
    int ar3 = (tid + 192) >> 4,  as3 = ((tid + 192) & 15) << 2;
    int br0 = tid >> 3,          bs0 = (tid & 7) << 2;
    int br1 = (tid + 64) >> 3,   bs1 = ((tid + 64) & 7) << 2;

    const float* Abase = At + row0;
    const float* Bbase = Bm + col0;

    u64 acc[4][4];     // 4 rows x 4 col-pairs (8 cols)
    #pragma unroll
    for (int i = 0; i < 4; i++)
        #pragma unroll
        for (int j = 0; j < 4; j++) acc[i][j] = 0ull;

    int nch = K >> 4;
    #pragma unroll
    for (int p = 0; p < 2; p++) {
        int kc = p << 4;
        cpa16(&As[p][ar0][as0], Abase + (size_t)(kc + ar0) * ldaT + as0);
        cpa16(&As[p][ar1][as1], Abase + (size_t)(kc + ar1) * ldaT + as1);
        cpa16(&As[p][ar2][as2], Abase + (size_t)(kc + ar2) * ldaT + as2);
        cpa16(&As[p][ar3][as3], Abase + (size_t)(kc + ar3) * ldaT + as3);
        cpa16(&Bs[p][br0][bs0], Bbase + (size_t)(kc + br0) * N + bs0);
        cpa16(&Bs[p][br1][bs1], Bbase + (size_t)(kc + br1) * N + bs1);
        asm volatile("cp.async.commit_group;");
    }

    int mrow = w * 32 + rg * 4;
    int ncol = cg * 8;
    int s = 0;
    for (int ch = 0; ch < nch; ch++) {
        if (ch < nch - 1) asm volatile("cp.async.wait_group 1;");
        else              asm volatile("cp.async.wait_group 0;");
        __syncthreads();

        if (ch + 2 < nch) {
            int s2 = s + 2; if (s2 >= STAGES) s2 -= STAGES;
            int kc = (ch + 2) << 4;
            cpa16(&As[s2][ar0][as0], Abase + (size_t)(kc + ar0) * ldaT + as0);
            cpa16(&As[s2][ar1][as1], Abase + (size_t)(kc + ar1) * ldaT + as1);
            cpa16(&As[s2][ar2][as2], Abase + (size_t)(kc + ar2) * ldaT + as2);
            cpa16(&As[s2][ar3][as3], Abase + (size_t)(kc + ar3) * ldaT + as3);
            cpa16(&Bs[s2][br0][bs0], Bbase + (size_t)(kc + br0) * N + bs0);
            cpa16(&Bs[s2][br1][bs1], Bbase + (size_t)(kc + br1) * N + bs1);
            asm volatile("cp.async.commit_group;");
        }

        #pragma unroll
        for (int k = 0; k < 16; k++) {
            float4 av = *(float4*)&As[s][k][mrow];
            ulonglong2 q0 = *(ulonglong2*)&Bs[s][k][ncol];
            ulonglong2 q1 = *(ulonglong2*)&Bs[s][k][ncol + 4];
            u64 a0, a1, a2, a3;
            PACKDUP(a0, av.x); PACKDUP(a1, av.y); PACKDUP(a2, av.z); PACKDUP(a3, av.w);
            FMA2(acc[0][0], a0, q0.x); FMA2(acc[0][1], a0, q0.y);
            FMA2(acc[0][2], a0, q1.x); FMA2(acc[0][3], a0, q1.y);
            FMA2(acc[1][0], a1, q0.x); FMA2(acc[1][1], a1, q0.y);
            FMA2(acc[1][2], a1, q1.x); FMA2(acc[1][3], a1, q1.y);
            FMA2(acc[2][0], a2, q0.x); FMA2(acc[2][1], a2, q0.y);
            FMA2(acc[2][2], a2, q1.x); FMA2(acc[2][3], a2, q1.y);
            FMA2(acc[3][0], a3, q0.x); FMA2(acc[3][1], a3, q0.y);
            FMA2(acc[3][2], a3, q1.x); FMA2(acc[3][3], a3, q1.y);
        }
        s++; if (s >= STAGES) s = 0;
    }

    // epilogue: 4 rows x 8 contiguous cols
    float vv[4][8];
    #pragma unroll
    for (int i = 0; i < 4; i++) {
        UNPACK2(vv[i][0], vv[i][1], acc[i][0]);
        UNPACK2(vv[i][2], vv[i][3], acc[i][1]);
        UNPACK2(vv[i][4], vv[i][5], acc[i][2]);
        UNPACK2(vv[i][6], vv[i][7], acc[i][3]);
    }
    int c0 = col0 + ncol;
    int r0 = row0 + mrow;
    #pragma unroll
    for (int j = 0; j < 8; j++) {
        float bj  = bias ? bias[c0 + j] : 0.f;
        float cvj = rowS ? colV[c0 + j] : 0.f;
        #pragma unroll
        for (int i = 0; i < 4; i++) {
            float rs = rowS ? rowS[r0 + i] : 0.f;
            float v = vv[i][j] + bj + rs * cvj;
            if (doRelu) v = fmaxf(v, 0.f);
            vv[i][j] = v;
        }
    }
    if (c0 < splitCol) {
        #pragma unroll
        for (int i = 0; i < 4; i++) {
            float4 o0 = {vv[i][0], vv[i][1], vv[i][2], vv[i][3]};
            float4 o1 = {vv[i][4], vv[i][5], vv[i][6], vv[i][7]};
            *(float4*)(Crow + (size_t)(r0 + i) * ldC + c0)     = o0;
            *(float4*)(Crow + (size_t)(r0 + i) * ldC + c0 + 4) = o1;
        }
    } else {
        #pragma unroll
        for (int j = 0; j < 8; j++) {
            float4 o = {vv[0][j], vv[1][j], vv[2][j], vv[3][j]};
            *(float4*)(CtrT + (size_t)(c0 + j - splitCol) * ldT + r0) = o;
        }
    }
}

// ---------------- prep: transposes + Wcat/bcat + bc ---------------------------
__global__ void prep(const float* __restrict__ X, const float* __restrict__ msgW2,
                     const float* __restrict__ msgW1, const float* __restrict__ Whh,
                     const float* __restrict__ msgb1, const float* __restrict__ bhh,
                     const float* __restrict__ msgb2, const float* __restrict__ Wih,
                     float* __restrict__ XT, float* __restrict__ M2T,
                     float* __restrict__ Wcat, float* __restrict__ bcat,
                     float* __restrict__ bc)
{
    int blk = blockIdx.x, t = threadIdx.x;
    if (blk < 256) {                     // XT[k][m] = X[m][k]
        int i = blk * 256 + t;
        int k = i >> 10, m = i & 1023;
        XT[i] = X[(size_t)m * Fn + k];
    } else if (blk < 512) {              // M2T[k][m] = msg_W2[m][k]
        int i = (blk - 256) * 256 + t;
        int k = i >> 8, m = i & 255;
        M2T[i] = msgW2[(size_t)m * Hn + k];
    } else if (blk < 1792) {             // Wcat[k][n]
        int i = (blk - 512) * 256 + t;
        int k = i / NC, n = i % NC;
        float v;
        if (n < 256)      v = msgW1[(size_t)k * Hn + n];
        else if (n < 512) v = msgW1[(size_t)(256 + k) * Hn + (n - 256)];
        else              v = Whh[(size_t)k * 768 + (n - 512)];
        Wcat[i] = v;
        if (i < NC)
            bcat[i] = i < 256 ? msgb1[i] : (i < 512 ? 0.f : bhh[i - 512]);
    } else {                             // bc = msg_b2 @ gru_Wih (one warp/output)
        int warp = (blk - 1792) * 8 + (t >> 5);
        int lane = t & 31;
        float s = 0.f;
        for (int k = lane; k < Hn; k += 32)
            s += msgb2[k] * Wih[(size_t)k * 768 + warp];
        #pragma unroll
        for (int o = 16; o; o >>= 1) s += __shfl_xor_sync(0xffffffffu, s, o);
        if (lane == 0) bc[warp] = s;
    }
}

// ---------------- E-aggregation ----------------------------------------------
#define IT 8
__global__ void eagg(const float* __restrict__ big2, const int* __restrict__ adj,
                     float* __restrict__ aT, float* __restrict__ deg)
{
    int b  = blockIdx.y;
    int i0 = blockIdx.x * IT;
    int h  = threadIdx.x;

    __shared__ float adjf[Nn][IT];

    float hir[IT], acc[IT];
    #pragma unroll
    for (int t = 0; t < IT; t++) {
        adjf[h][t] = (float)adj[((size_t)(b * Nn + i0 + t)) * Nn + h];
        hir[t] = big2[((size_t)(b * Nn + i0 + t)) * 512 + h];
        acc[t] = 0.f;
    }
    __syncthreads();

    const float* hjb = big2 + (size_t)b * Nn * 512 + 256;
    #pragma unroll 2
    for (int j = 0; j < Nn; j++) {
        float hjv = hjb[(size_t)j * 512 + h];
        float4 a04 = *(float4*)&adjf[j][0];
        float4 a47 = *(float4*)&adjf[j][4];
        acc[0] += a04.x * fmaxf(hir[0] + hjv, 0.f);
        acc[1] += a04.y * fmaxf(hir[1] + hjv, 0.f);
        acc[2] += a04.z * fmaxf(hir[2] + hjv, 0.f);
        acc[3] += a04.w * fmaxf(hir[3] + hjv, 0.f);
        acc[4] += a47.x * fmaxf(hir[4] + hjv, 0.f);
        acc[5] += a47.y * fmaxf(hir[5] + hjv, 0.f);
        acc[6] += a47.z * fmaxf(hir[6] + hjv, 0.f);
        acc[7] += a47.w * fmaxf(hir[7] + hjv, 0.f);
    }

    #pragma unroll
    for (int t = 0; t < IT; t++)
        aT[(size_t)h * BN + b * Nn + i0 + t] = acc[t];

    if (h < IT) {
        float s = 0.f;
        for (int j = 0; j < Nn; j++) s += adjf[j][h];
        deg[b * Nn + i0 + h] = s;
    }
}

// ---------------- GRU elementwise (coalesced on transposed layouts) ----------
__global__ void gru(const float* __restrict__ giT, const float* __restrict__ ghT,
                    float* __restrict__ hT)
{
    int id = blockIdx.x * 256 + threadIdx.x;
    int m = id & 1023, c = id >> 10;
    float ir = giT[(size_t)c * BN + m];
    float iz = giT[(size_t)(c + 256) * BN + m];
    float in = giT[(size_t)(c + 512) * BN + m];
    float hr = ghT[(size_t)c * BN + m];
    float hz = ghT[(size_t)(c + 256) * BN + m];
    float hn = ghT[(size_t)(c + 512) * BN + m];
    float r = 1.f / (1.f + __expf(-(ir + hr)));
    float z = 1.f / (1.f + __expf(-(iz + hz)));
    float n = tanhf(in + r * hn);
    hT[id] = (1.f - z) * n + z * hT[id];
}

// ---------------- readout ------------------------------------------------------
__global__ void readout(const float* __restrict__ hT,
                        const float* __restrict__ W1, const float* __restrict__ b1,
                        const float* __restrict__ W2, const float* __restrict__ b2,
                        float* __restrict__ out)
{
    __shared__ float gsh[Hn];
    __shared__ float hsh[Hn];
    int b = blockIdx.x, t = threadIdx.x;

    float s = 0.f;
    const float* hrow = hT + (size_t)t * BN + b * Nn;
    #pragma unroll 4
    for (int i = 0; i < Nn; i++) s += hrow[i];
    gsh[t] = s;
    __syncthreads();

    float s2 = b1[t];
    for (int k = 0; k < Hn; k++) s2 += gsh[k] * W1[(size_t)k * Hn + t];
    hsh[t] = fmaxf(s2, 0.f);
    __syncthreads();

    if (t < An) {
        float s3 = b2[t];
        for (int k = 0; k < Hn; k++) s3 += hsh[k] * W2[(size_t)k * An + t];
        out[b * An + t] = s3;
    }
}

// ---------------- host launch ---------------------------------------------------
extern "C" void kernel_launch(void* const* d_in, const int* in_sizes, int n_in,
                              void* d_out, int out_size)
{
    const float* X       = (const float*)d_in[0];
    const int*   adj     = (const int*)  d_in[1];
    const float* pre_W1  = (const float*)d_in[2];
    const float* pre_b1  = (const float*)d_in[3];
    const float* pre_W2  = (const float*)d_in[4];
    const float* pre_b2  = (const float*)d_in[5];
    const float* msg_W1  = (const float*)d_in[6];
    const float* msg_b1  = (const float*)d_in[7];
    const float* msg_W2  = (const float*)d_in[8];
    const float* msg_b2  = (const float*)d_in[9];
    const float* gru_Wih = (const float*)d_in[10];
    const float* gru_Whh = (const float*)d_in[11];
    const float* gru_bih = (const float*)d_in[12];
    const float* gru_bhh = (const float*)d_in[13];
    const float* ro_W1   = (const float*)d_in[14];
    const float* ro_b1   = (const float*)d_in[15];
    const float* ro_W2   = (const float*)d_in[16];
    const float* ro_b2   = (const float*)d_in[17];

    float *XT,*tT,*hT,*aT,*M2T,*big2,*ghT,*giT,*deg,*Wc,*bc,*Wcat,*bcat;
    cudaGetSymbolAddress((void**)&XT,  d_XT);
    cudaGetSymbolAddress((void**)&tT,  d_tT);
    cudaGetSymbolAddress((void**)&hT,  d_hT);
    cudaGetSymbolAddress((void**)&aT,  d_aT);
    cudaGetSymbolAddress((void**)&M2T, d_M2T);
    cudaGetSymbolAddress((void**)&big2,d_big2);
    cudaGetSymbolAddress((void**)&ghT, d_ghT);
    cudaGetSymbolAddress((void**)&giT, d_giT);
    cudaGetSymbolAddress((void**)&deg, d_deg);
    cudaGetSymbolAddress((void**)&Wc,  d_Wc);
    cudaGetSymbolAddress((void**)&bc,  d_bc);
    cudaGetSymbolAddress((void**)&Wcat,d_Wcat);
    cudaGetSymbolAddress((void**)&bcat,d_bcat);

    // prep: XT, M2T, Wcat, bcat, bc  (512 + 1280 + 96 blocks)
    prep<<<1888, 256>>>(X, msg_W2, msg_W1, gru_Whh, msg_b1, gru_bhh, msg_b2, gru_Wih,
                        XT, M2T, Wcat, bcat, bc);

    // Wc = msg_W2 @ gru_Wih: M=256, N=768, K=256 -> grid (24, 4)
    gemmS<<<dim3(768/32, 256/64), 64>>>(M2T, Hn, gru_Wih, 768, Hn,
                                        nullptr, nullptr, nullptr,
                                        Wc, 768, 768, nullptr, 0, 0);

    // pre-MLP: tT = relu(X@W1+b1)^T ; hT = (t@W2+b2)^T   -> grid (8, 16)
    gemmS<<<dim3(256/32, BN/64), 64>>>(XT, BN, pre_W1, Hn, Fn,
                                       pre_b1, nullptr, nullptr,
                                       nullptr, 0, 0, tT, BN, 1);
    gemmS<<<dim3(256/32, BN/64), 64>>>(tT, BN, pre_W2, Hn, Hn,
                                       pre_b2, nullptr, nullptr,
                                       nullptr, 0, 0, hT, BN, 0);

    for (int it = 0; it < Tn; it++) {
        // [hi+b1 | hj] -> big2 (row-major), gh+bhh -> ghT (transposed). grid (40,16)
        gemmS<<<dim3(NC/32, BN/64), 64>>>(hT, BN, Wcat, NC, Hn,
                                          bcat, nullptr, nullptr,
                                          big2, 512, 512, ghT, BN, 0);
        eagg<<<dim3(Nn / IT, Bn), 256>>>(big2, adj, aT, deg);
        // giT = (agg0 @ Wc + deg*bc + bih)^T. grid (24,16)
        gemmS<<<dim3(768/32, BN/64), 64>>>(aT, BN, Wc, 768, Hn,
                                           gru_bih, deg, bc,
                                           nullptr, 0, 0, giT, BN, 0);
        gru<<<Hn * BN / 256, 256>>>(giT, ghT, hT);
    }

    readout<<<Bn, 256>>>(hT, ro_W1, ro_b1, ro_W2, ro_b2, (float*)d_out);
}

// round 17
// speedup vs baseline: 1.1949x; 1.0254x over previous
#include <cuda_runtime.h>
#include <cuda_bf16.h>
#include <math.h>
#include <stdint.h>

// Shapes: B=4, N=256, F=64, H=256, A=16, T=3
#define Bn 4
#define Nn 256
#define Fn 64
#define Hn 256
#define An 16
#define Tn 3
#define BN 1024
#define NC 1280
#define STG 4

typedef unsigned long long u64;

// ---------------- scratch (device globals) -----------------------------------
__device__ float d_XT  [Fn*BN];      // X^T        [64][1024]
__device__ float d_tT  [Hn*BN];      // pre-hidden^T
__device__ float d_hT  [Hn*BN];      // h^T
__device__ float d_aT  [Hn*BN];      // agg0^T
__device__ float d_M2T [Hn*Hn];      // msg_W2^T
__device__ float d_big2[BN*512];     // [hi+b1 | hj] row-major
__device__ float d_ghT [768*BN];     // gh^T (+bhh)
__device__ float d_giT [768*BN];     // gi^T
__device__ float d_deg [BN];
__device__ float d_Wc  [Hn*768];     // msg_W2 @ gru_Wih (row-major)
__device__ float d_bc  [768];        // msg_b2 @ gru_Wih
__device__ float d_Wcat[Hn*NC];      // [W1_i | W1_j | Whh] row-major
__device__ float d_bcat[NC];

// ---------------- helpers ------------------------------------------------------
#define FMA2(acc, a, b) \
    asm("fma.rn.f32x2 %0, %1, %2, %0;" : "+l"(acc) : "l"(a), "l"(b))
#define PACKDUP(d, s) \
    asm("mov.b64 %0, {%1, %1};" : "=l"(d) : "f"(s))
#define UNPACK2(lo, hi, s) \
    asm("mov.b64 {%0, %1}, %2;" : "=f"(lo), "=f"(hi) : "l"(s))

__device__ __forceinline__ void cpa16(void* s, const void* g) {
    uint32_t sa = (uint32_t)__cvta_generic_to_shared(s);
    asm volatile("cp.async.ca.shared.global [%0], [%1], 16;" :: "r"(sa), "l"(g));
}

// ---------------- single-warp pipelined fp32 GEMM, 32x32 tile ------------------
// One warp per block: loads AND computes -> NO __syncthreads, only __syncwarp.
// C = f(A@B + bias + rowS*colV); A TRANSPOSED At[k][m] (ld ldaT); B row-major KxN.
// Thread: 4 rows x 8 contiguous cols (16 FMA2 + 3 LDS.128 + 4 PACKDUP / k-step).
// 4-stage cp.async pipeline (lead 3), K-chunks of 16, K mult 16, K>=64.
// M,N mult 32. Block col < splitCol -> Crow[r][c] (ld ldC);
// else CtrT[(c-splitCol)][r] (ld ldT).
__global__ void __launch_bounds__(32)
gemm1w(const float* __restrict__ At, int ldaT,
       const float* __restrict__ Bm, int N, int K,
       const float* __restrict__ bias,
       const float* __restrict__ rowS, const float* __restrict__ colV,
       float* __restrict__ Crow, int ldC, int splitCol,
       float* __restrict__ CtrT, int ldT, int doRelu)
{
    __shared__ __align__(16) float As[STG][16][36];   // 32 m + 4 pad
    __shared__ __align__(16) float Bs[STG][16][32];

    int tid = threadIdx.x;
    int rg = tid >> 2, cg = tid & 3;          // 8 row-groups x 4 col-groups
    int row0 = blockIdx.y * 32, col0 = blockIdx.x * 32;

    // loaders: per chunk A = 128 f4 (4/thread), B = 128 f4 (4/thread)
    int lr[4], ls[4];
    #pragma unroll
    for (int i = 0; i < 4; i++) {
        int idx = tid + 32 * i;
        lr[i] = idx >> 3;              // k row 0..15
        ls[i] = (idx & 7) << 2;        // 16B seg
    }

    const float* Abase = At + row0;
    const float* Bbase = Bm + col0;

    u64 acc[4][4];
    #pragma unroll
    for (int i = 0; i < 4; i++)
        #pragma unroll
        for (int j = 0; j < 4; j++) acc[i][j] = 0ull;

    int nch = K >> 4;
    // prologue: 3 chunks
    #pragma unroll
    for (int p = 0; p < 3; p++) {
        int kc = p << 4;
        #pragma unroll
        for (int i = 0; i < 4; i++) {
            cpa16(&As[p][lr[i]][ls[i]], Abase + (size_t)(kc + lr[i]) * ldaT + ls[i]);
            cpa16(&Bs[p][lr[i]][ls[i]], Bbase + (size_t)(kc + lr[i]) * N + ls[i]);
        }
        asm volatile("cp.async.commit_group;");
    }

    int mrow = rg * 4;
    int ncol = cg * 8;
    int s = 0;
    for (int ch = 0; ch < nch; ch++) {
        if (ch < nch - 2)       asm volatile("cp.async.wait_group 2;");
        else if (ch == nch - 2) asm volatile("cp.async.wait_group 1;");
        else                    asm volatile("cp.async.wait_group 0;");
        __syncwarp();

        if (ch + 3 < nch) {
            int s3 = s + 3; if (s3 >= STG) s3 -= STG;
            int kc = (ch + 3) << 4;
            #pragma unroll
            for (int i = 0; i < 4; i++) {
                cpa16(&As[s3][lr[i]][ls[i]], Abase + (size_t)(kc + lr[i]) * ldaT + ls[i]);
                cpa16(&Bs[s3][lr[i]][ls[i]], Bbase + (size_t)(kc + lr[i]) * N + ls[i]);
            }
            asm volatile("cp.async.commit_group;");
        }

        #pragma unroll
        for (int k = 0; k < 16; k++) {
            float4 av = *(float4*)&As[s][k][mrow];
            ulonglong2 q0 = *(ulonglong2*)&Bs[s][k][ncol];
            ulonglong2 q1 = *(ulonglong2*)&Bs[s][k][ncol + 4];
            u64 a0, a1, a2, a3;
            PACKDUP(a0, av.x); PACKDUP(a1, av.y); PACKDUP(a2, av.z); PACKDUP(a3, av.w);
            FMA2(acc[0][0], a0, q0.x); FMA2(acc[0][1], a0, q0.y);
            FMA2(acc[0][2], a0, q1.x); FMA2(acc[0][3], a0, q1.y);
            FMA2(acc[1][0], a1, q0.x); FMA2(acc[1][1], a1, q0.y);
            FMA2(acc[1][2], a1, q1.x); FMA2(acc[1][3], a1, q1.y);
            FMA2(acc[2][0], a2, q0.x); FMA2(acc[2][1], a2, q0.y);
            FMA2(acc[2][2], a2, q1.x); FMA2(acc[2][3], a2, q1.y);
            FMA2(acc[3][0], a3, q0.x); FMA2(acc[3][1], a3, q0.y);
            FMA2(acc[3][2], a3, q1.x); FMA2(acc[3][3], a3, q1.y);
        }
        s++; if (s >= STG) s = 0;
    }

    // epilogue: 4 rows x 8 contiguous cols
    float vv[4][8];
    #pragma unroll
    for (int i = 0; i < 4; i++) {
        UNPACK2(vv[i][0], vv[i][1], acc[i][0]);
        UNPACK2(vv[i][2], vv[i][3], acc[i][1]);
        UNPACK2(vv[i][4], vv[i][5], acc[i][2]);
        UNPACK2(vv[i][6], vv[i][7], acc[i][3]);
    }
    int c0 = col0 + ncol;
    int r0 = row0 + mrow;
    #pragma unroll
    for (int j = 0; j < 8; j++) {
        float bj  = bias ? bias[c0 + j] : 0.f;
        float cvj = rowS ? colV[c0 + j] : 0.f;
        #pragma unroll
        for (int i = 0; i < 4; i++) {
            float rs = rowS ? rowS[r0 + i] : 0.f;
            float v = vv[i][j] + bj + rs * cvj;
            if (doRelu) v = fmaxf(v, 0.f);
            vv[i][j] = v;
        }
    }
    if (c0 < splitCol) {
        #pragma unroll
        for (int i = 0; i < 4; i++) {
            float4 o0 = {vv[i][0], vv[i][1], vv[i][2], vv[i][3]};
            float4 o1 = {vv[i][4], vv[i][5], vv[i][6], vv[i][7]};
            *(float4*)(Crow + (size_t)(r0 + i) * ldC + c0)     = o0;
            *(float4*)(Crow + (size_t)(r0 + i) * ldC + c0 + 4) = o1;
        }
    } else {
        #pragma unroll
        for (int j = 0; j < 8; j++) {
            float4 o = {vv[0][j], vv[1][j], vv[2][j], vv[3][j]};
            *(float4*)(CtrT + (size_t)(c0 + j - splitCol) * ldT + r0) = o;
        }
    }
}

// ---------------- prep: transposes + Wcat/bcat + bc ---------------------------
__global__ void prep(const float* __restrict__ X, const float* __restrict__ msgW2,
                     const float* __restrict__ msgW1, const float* __restrict__ Whh,
                     const float* __restrict__ msgb1, const float* __restrict__ bhh,
                     const float* __restrict__ msgb2, const float* __restrict__ Wih,
                     float* __restrict__ XT, float* __restrict__ M2T,
                     float* __restrict__ Wcat, float* __restrict__ bcat,
                     float* __restrict__ bc)
{
    int blk = blockIdx.x, t = threadIdx.x;
    if (blk < 256) {                     // XT[k][m] = X[m][k]
        int i = blk * 256 + t;
        int k = i >> 10, m = i & 1023;
        XT[i] = X[(size_t)m * Fn + k];
    } else if (blk < 512) {              // M2T[k][m] = msg_W2[m][k]
        int i = (blk - 256) * 256 + t;
        int k = i >> 8, m = i & 255;
        M2T[i] = msgW2[(size_t)m * Hn + k];
    } else if (blk < 1792) {             // Wcat[k][n]
        int i = (blk - 512) * 256 + t;
        int k = i / NC, n = i % NC;
        float v;
        if (n < 256)      v = msgW1[(size_t)k * Hn + n];
        else if (n < 512) v = msgW1[(size_t)(256 + k) * Hn + (n - 256)];
        else              v = Whh[(size_t)k * 768 + (n - 512)];
        Wcat[i] = v;
        if (i < NC)
            bcat[i] = i < 256 ? msgb1[i] : (i < 512 ? 0.f : bhh[i - 512]);
    } else {                             // bc = msg_b2 @ gru_Wih (one warp/output)
        int warp = (blk - 1792) * 8 + (t >> 5);
        int lane = t & 31;
        float s = 0.f;
        for (int k = lane; k < Hn; k += 32)
            s += msgb2[k] * Wih[(size_t)k * 768 + warp];
        #pragma unroll
        for (int o = 16; o; o >>= 1) s += __shfl_xor_sync(0xffffffffu, s, o);
        if (lane == 0) bc[warp] = s;
    }
}

// ---------------- E-aggregation ----------------------------------------------
#define IT 8
__global__ void eagg(const float* __restrict__ big2, const int* __restrict__ adj,
                     float* __restrict__ aT, float* __restrict__ deg)
{
    int b  = blockIdx.y;
    int i0 = blockIdx.x * IT;
    int h  = threadIdx.x;

    __shared__ float adjf[Nn][IT];

    float hir[IT], acc[IT];
    #pragma unroll
    for (int t = 0; t < IT; t++) {
        adjf[h][t] = (float)adj[((size_t)(b * Nn + i0 + t)) * Nn + h];
        hir[t] = big2[((size_t)(b * Nn + i0 + t)) * 512 + h];
        acc[t] = 0.f;
    }
    __syncthreads();

    const float* hjb = big2 + (size_t)b * Nn * 512 + 256;
    #pragma unroll 2
    for (int j = 0; j < Nn; j++) {
        float hjv = hjb[(size_t)j * 512 + h];
        float4 a04 = *(float4*)&adjf[j][0];
        float4 a47 = *(float4*)&adjf[j][4];
        acc[0] += a04.x * fmaxf(hir[0] + hjv, 0.f);
        acc[1] += a04.y * fmaxf(hir[1] + hjv, 0.f);
        acc[2] += a04.z * fmaxf(hir[2] + hjv, 0.f);
        acc[3] += a04.w * fmaxf(hir[3] + hjv, 0.f);
        acc[4] += a47.x * fmaxf(hir[4] + hjv, 0.f);
        acc[5] += a47.y * fmaxf(hir[5] + hjv, 0.f);
        acc[6] += a47.z * fmaxf(hir[6] + hjv, 0.f);
        acc[7] += a47.w * fmaxf(hir[7] + hjv, 0.f);
    }

    #pragma unroll
    for (int t = 0; t < IT; t++)
        aT[(size_t)h * BN + b * Nn + i0 + t] = acc[t];

    if (h < IT) {
        float s = 0.f;
        for (int j = 0; j < Nn; j++) s += adjf[j][h];
        deg[b * Nn + i0 + h] = s;
    }
}

// ---------------- GRU elementwise (coalesced on transposed layouts) ----------
__global__ void gru(const float* __restrict__ giT, const float* __restrict__ ghT,
                    float* __restrict__ hT)
{
    int id = blockIdx.x * 256 + threadIdx.x;
    int m = id & 1023, c = id >> 10;
    float ir = giT[(size_t)c * BN + m];
    float iz = giT[(size_t)(c + 256) * BN + m];
    float in = giT[(size_t)(c + 512) * BN + m];
    float hr = ghT[(size_t)c * BN + m];
    float hz = ghT[(size_t)(c + 256) * BN + m];
    float hn = ghT[(size_t)(c + 512) * BN + m];
    float r = 1.f / (1.f + __expf(-(ir + hr)));
    float z = 1.f / (1.f + __expf(-(iz + hz)));
    float n = tanhf(in + r * hn);
    hT[id] = (1.f - z) * n + z * hT[id];
}

// ---------------- readout ------------------------------------------------------
__global__ void readout(const float* __restrict__ hT,
                        const float* __restrict__ W1, const float* __restrict__ b1,
                        const float* __restrict__ W2, const float* __restrict__ b2,
                        float* __restrict__ out)
{
    __shared__ float gsh[Hn];
    __shared__ float hsh[Hn];
    int b = blockIdx.x, t = threadIdx.x;

    float s = 0.f;
    const float* hrow = hT + (size_t)t * BN + b * Nn;
    #pragma unroll 4
    for (int i = 0; i < Nn; i++) s += hrow[i];
    gsh[t] = s;
    __syncthreads();

    float s2 = b1[t];
    for (int k = 0; k < Hn; k++) s2 += gsh[k] * W1[(size_t)k * Hn + t];
    hsh[t] = fmaxf(s2, 0.f);
    __syncthreads();

    if (t < An) {
        float s3 = b2[t];
        for (int k = 0; k < Hn; k++) s3 += hsh[k] * W2[(size_t)k * An + t];
        out[b * An + t] = s3;
    }
}

// ---------------- host launch ---------------------------------------------------
extern "C" void kernel_launch(void* const* d_in, const int* in_sizes, int n_in,
                              void* d_out, int out_size)
{
    const float* X       = (const float*)d_in[0];
    const int*   adj     = (const int*)  d_in[1];
    const float* pre_W1  = (const float*)d_in[2];
    const float* pre_b1  = (const float*)d_in[3];
    const float* pre_W2  = (const float*)d_in[4];
    const float* pre_b2  = (const float*)d_in[5];
    const float* msg_W1  = (const float*)d_in[6];
    const float* msg_b1  = (const float*)d_in[7];
    const float* msg_W2  = (const float*)d_in[8];
    const float* msg_b2  = (const float*)d_in[9];
    const float* gru_Wih = (const float*)d_in[10];
    const float* gru_Whh = (const float*)d_in[11];
    const float* gru_bih = (const float*)d_in[12];
    const float* gru_bhh = (const float*)d_in[13];
    const float* ro_W1   = (const float*)d_in[14];
    const float* ro_b1   = (const float*)d_in[15];
    const float* ro_W2   = (const float*)d_in[16];
    const float* ro_b2   = (const float*)d_in[17];

    float *XT,*tT,*hT,*aT,*M2T,*big2,*ghT,*giT,*deg,*Wc,*bc,*Wcat,*bcat;
    cudaGetSymbolAddress((void**)&XT,  d_XT);
    cudaGetSymbolAddress((void**)&tT,  d_tT);
    cudaGetSymbolAddress((void**)&hT,  d_hT);
    cudaGetSymbolAddress((void**)&aT,  d_aT);
    cudaGetSymbolAddress((void**)&M2T, d_M2T);
    cudaGetSymbolAddress((void**)&big2,d_big2);
    cudaGetSymbolAddress((void**)&ghT, d_ghT);
    cudaGetSymbolAddress((void**)&giT, d_giT);
    cudaGetSymbolAddress((void**)&deg, d_deg);
    cudaGetSymbolAddress((void**)&Wc,  d_Wc);
    cudaGetSymbolAddress((void**)&bc,  d_bc);
    cudaGetSymbolAddress((void**)&Wcat,d_Wcat);
    cudaGetSymbolAddress((void**)&bcat,d_bcat);

    // prep: XT, M2T, Wcat, bcat, bc
    prep<<<1888, 256>>>(X, msg_W2, msg_W1, gru_Whh, msg_b1, gru_bhh, msg_b2, gru_Wih,
                        XT, M2T, Wcat, bcat, bc);

    // Wc = msg_W2 @ gru_Wih: grid (24, 8)
    gemm1w<<<dim3(768/32, 256/32), 32>>>(M2T, Hn, gru_Wih, 768, Hn,
                                         nullptr, nullptr, nullptr,
                                         Wc, 768, 768, nullptr, 0, 0);

    // pre-MLP: tT = relu(X@W1+b1)^T ; hT = (t@W2+b2)^T   grid (8, 32)
    gemm1w<<<dim3(256/32, BN/32), 32>>>(XT, BN, pre_W1, Hn, Fn,
                                        pre_b1, nullptr, nullptr,
                                        nullptr, 0, 0, tT, BN, 1);
    gemm1w<<<dim3(256/32, BN/32), 32>>>(tT, BN, pre_W2, Hn, Hn,
                                        pre_b2, nullptr, nullptr,
                                        nullptr, 0, 0, hT, BN, 0);

    for (int it = 0; it < Tn; it++) {
        // [hi+b1 | hj] -> big2 (row-major), gh+bhh -> ghT (transposed). grid (40,32)
        gemm1w<<<dim3(NC/32, BN/32), 32>>>(hT, BN, Wcat, NC, Hn,
                                           bcat, nullptr, nullptr,
                                           big2, 512, 512, ghT, BN, 0);
        eagg<<<dim3(Nn / IT, Bn), 256>>>(big2, adj, aT, deg);
        // giT = (agg0 @ Wc + deg*bc + bih)^T. grid (24,32)
        gemm1w<<<dim3(768/32, BN/32), 32>>>(aT, BN, Wc, 768, Hn,
                                            gru_bih, deg, bc,
                                            nullptr, 0, 0, giT, BN, 0);
        gru<<<Hn * BN / 256, 256>>>(giT, ghT, hT);
    }

    readout<<<Bn, 256>>>(hT, ro_W1, ro_b1, ro_W2, ro_b2, (float*)d_out);
}